// round 5
// baseline (speedup 1.0000x reference)
#include <cuda_runtime.h>
#include <math.h>
#include <stdint.h>

#define D_DIM 1536
#define E_NUM 64
#define H_DIM 384
#define TOPK  8
#define CAP   1024
#define T_NUM 4096

// ---------------- scratch (static device globals; no allocations) ----------
__device__ __align__(16) int   g_counts[E_NUM];
__device__ __align__(16) int   g_slot_token[E_NUM * CAP];
__device__ __align__(16) float g_slot_weight[E_NUM * CAP];
__device__ __align__(16) int   g_tok_slot[T_NUM * TOPK];
__device__ __align__(16) float g_act[(size_t)E_NUM * CAP * H_DIM];  // ~100 MB
__device__ __align__(16) float g_y[(size_t)E_NUM * CAP * D_DIM];    // ~402 MB

// ---------------- helpers ----------------------------------------------------
__device__ __forceinline__ uint32_t tf32_rna(float x) {
    uint32_t r; asm("cvt.rna.tf32.f32 %0, %1;" : "=r"(r) : "f"(x)); return r;
}
__device__ __forceinline__ void mma1688(float c[4],
                                        uint32_t a0, uint32_t a1, uint32_t a2, uint32_t a3,
                                        uint32_t b0, uint32_t b1) {
    asm volatile(
        "mma.sync.aligned.m16n8k8.row.col.f32.tf32.tf32.f32 "
        "{%0,%1,%2,%3}, {%4,%5,%6,%7}, {%8,%9}, {%0,%1,%2,%3};"
        : "+f"(c[0]), "+f"(c[1]), "+f"(c[2]), "+f"(c[3])
        : "r"(a0), "r"(a1), "r"(a2), "r"(a3), "r"(b0), "r"(b1));
}
__device__ __forceinline__ float silu(float g) { return g / (1.f + expf(-g)); }

// ---------------- kernel 0: init counters -----------------------------------
__global__ void init_kernel() {
    if (threadIdx.x < E_NUM) g_counts[threadIdx.x] = 0;
}

// ---------------- kernel 1: router ------------------------------------------
extern __shared__ float s_dyn[];

__global__ __launch_bounds__(256) void router_kernel(
    const float* __restrict__ x, const float* __restrict__ gate_w)
{
    float (*xs)[D_DIM] = (float (*)[D_DIM])s_dyn;
    float (*lg)[E_NUM] = (float (*)[E_NUM])(s_dyn + 8 * D_DIM);

    const int tid = threadIdx.x;
    const int t0 = blockIdx.x * 8;

    const float4* xg = (const float4*)(x + (size_t)t0 * D_DIM);
    float4* xs4 = (float4*)xs;
    for (int i = tid; i < 8 * D_DIM / 4; i += 256) xs4[i] = xg[i];
    __syncthreads();

    const int warp = tid >> 5, lane = tid & 31;

    for (int j = 0; j < 8; j++) {
        const int e = warp * 8 + j;
        const float4* gr = (const float4*)(gate_w + (size_t)e * D_DIM);
        float acc[8];
#pragma unroll
        for (int t = 0; t < 8; t++) acc[t] = 0.f;
        for (int d4 = lane; d4 < D_DIM / 4; d4 += 32) {
            float4 g = gr[d4];
#pragma unroll
            for (int t = 0; t < 8; t++) {
                float4 xv = *(const float4*)(&xs[t][d4 * 4]);
                acc[t] = fmaf(g.x, xv.x, fmaf(g.y, xv.y,
                          fmaf(g.z, xv.z, fmaf(g.w, xv.w, acc[t]))));
            }
        }
#pragma unroll
        for (int off = 16; off > 0; off >>= 1)
#pragma unroll
            for (int t = 0; t < 8; t++)
                acc[t] += __shfl_xor_sync(0xffffffffu, acc[t], off);
        if (lane == 0)
#pragma unroll
            for (int t = 0; t < 8; t++) lg[t][e] = acc[t];
    }
    __syncthreads();

    {
        const int t = warp;
        float v0 = lg[t][lane];
        float v1 = lg[t][lane + 32];
        float m = fmaxf(v0, v1);
#pragma unroll
        for (int off = 16; off > 0; off >>= 1)
            m = fmaxf(m, __shfl_xor_sync(0xffffffffu, m, off));
        float e0 = expf(v0 - m), e1 = expf(v1 - m);
        float s = e0 + e1;
#pragma unroll
        for (int off = 16; off > 0; off >>= 1)
            s += __shfl_xor_sync(0xffffffffu, s, off);
        float p0 = e0 / s, p1 = e1 / s;

        float selw[TOPK];
        int   sele[TOPK];
#pragma unroll
        for (int k = 0; k < TOPK; k++) {
            float bv; int bi;
            if (p0 >= p1) { bv = p0; bi = lane; }
            else          { bv = p1; bi = lane + 32; }
#pragma unroll
            for (int off = 16; off > 0; off >>= 1) {
                float ov = __shfl_xor_sync(0xffffffffu, bv, off);
                int   oi = __shfl_xor_sync(0xffffffffu, bi, off);
                if (ov > bv || (ov == bv && oi < bi)) { bv = ov; bi = oi; }
            }
            selw[k] = bv; sele[k] = bi;
            if (bi == lane)      p0 = -1.f;
            if (bi == lane + 32) p1 = -1.f;
        }
        float wsum = 0.f;
#pragma unroll
        for (int k = 0; k < TOPK; k++) wsum += selw[k];

        if (lane == 0) {
            const int tok = t0 + t;
#pragma unroll
            for (int k = 0; k < TOPK; k++) {
                const int e = sele[k];
                const int pos = atomicAdd(&g_counts[e], 1);
                if (pos < CAP) {
                    g_slot_token[e * CAP + pos]  = tok;
                    g_slot_weight[e * CAP + pos] = selw[k] / wsum;
                    g_tok_slot[tok * TOPK + k]   = e * CAP + pos;
                } else {
                    g_tok_slot[tok * TOPK + k]   = -1;
                }
            }
        }
    }
}

// =============================================================================
// Fragment-major smem layouts (per 16-k chunk):
//   A (M=128): 16 tiles (mt 0..7, kt 0..1), per tile 32 lanes x quad(4 u32).
//     quad j: 0=(g,t) 1=(g+8,t) 2=(g,t+4) 3=(g+8,t+4). -> compute LDS.128.
//   B (N cols): tiles (nt, kt), per tile 32 lanes x pair(2 u32).
//     pair j: 0=(n=8nt+g, k=t) 1=(n, k=t+4). -> compute LDS.64.
// Staging: warp == one tile -> STS.128/STS.64 fully contiguous, conflict-free.
// =============================================================================

// ---------------- kernel 2: grouped GEMM1 (tf32 mma, SwiGLU) ----------------
// CTA 128(M) x 128(H), 8 warps (2M x 4N), warp 64x32 DUAL (gate+up).
// dyn smem u32: A[0,4096) Bg[4096,8192) Bu[8192,12288); buf stride 2048.
__global__ __launch_bounds__(256) void gemm1_kernel(
    const float* __restrict__ x,
    const float* __restrict__ Wg,
    const float* __restrict__ Wu)
{
    const int e = blockIdx.z;
    const int n_e = min(g_counts[e], CAP);
    const int row0 = blockIdx.x * 128;
    if (row0 >= n_e) return;
    const int col0 = blockIdx.y * 128;

    extern __shared__ uint32_t su[];
    uint32_t* As = su;
    uint32_t* Bg = su + 4096;
    uint32_t* Bu = su + 8192;
    __shared__ int stok[128];

    const int tid = threadIdx.x, lane = tid & 31, wid = tid >> 5;
    const int g = lane >> 2, t = lane & 3;

    if (tid < 128) {
        const int r = row0 + tid;
        stok[tid] = (r < n_e) ? g_slot_token[e * CAP + r] : 0;
    }
    __syncthreads();

    // ---- staging descriptors (hoisted) ----
    const float* xp0[2]; const float* xp1[2]; uint32_t a_sts[2];
#pragma unroll
    for (int p = 0; p < 2; p++) {
        const int tile = (tid >> 5) + 8 * p;        // 0..15
        const int mt = tile >> 1, kta = tile & 1;
        const int r0 = 16 * mt + g;
        xp0[p] = x + (size_t)stok[r0] * D_DIM + 8 * kta + t;
        xp1[p] = x + (size_t)stok[r0 + 8] * D_DIM + 8 * kta + t;
        a_sts[p] = (uint32_t)(tile * 32 + lane) * 4;
    }
    const float* wg_e = Wg + (size_t)e * D_DIM * H_DIM;
    const float* wu_e = Wu + (size_t)e * D_DIM * H_DIM;
    const float* bgp[4]; const float* bup[4]; uint32_t b_sts[4];
#pragma unroll
    for (int p = 0; p < 4; p++) {
        const int tile = (tid >> 5) + 8 * p;        // 0..31
        const int nt = tile >> 1, ktb = tile & 1;
        const int h = col0 + 8 * nt + g;
        bgp[p] = wg_e + (size_t)(8 * ktb + t) * H_DIM + h;
        bup[p] = wu_e + (size_t)(8 * ktb + t) * H_DIM + h;
        b_sts[p] = (uint32_t)(tile * 32 + lane) * 2;
    }

    const int wm = wid >> 2, wn = wid & 3;
    float accg[4][4][4] = {}, accu[4][4][4] = {};

    const int NCH = D_DIM / 16;  // 96

    // ---- prologue: stage chunk 0 into buf 0 ----
#pragma unroll
    for (int p = 0; p < 2; p++) {
        *(uint4*)&As[a_sts[p]] = make_uint4(
            tf32_rna(xp0[p][0]), tf32_rna(xp1[p][0]),
            tf32_rna(xp0[p][4]), tf32_rna(xp1[p][4]));
    }
#pragma unroll
    for (int p = 0; p < 4; p++) {
        *(uint2*)&Bg[b_sts[p]] = make_uint2(
            tf32_rna(bgp[p][0]), tf32_rna(bgp[p][4 * (size_t)H_DIM]));
        *(uint2*)&Bu[b_sts[p]] = make_uint2(
            tf32_rna(bup[p][0]), tf32_rna(bup[p][4 * (size_t)H_DIM]));
    }
    __syncthreads();

    int buf = 0;
    for (int c = 0; c < NCH; c++) {
        // prefetch next chunk (raw floats)
        float pa[2][4], pg[4][2], pu[4][2];
        const bool pre = (c + 1 < NCH);
        if (pre) {
            const int kk = (c + 1) * 16;
            const size_t bo = (size_t)kk * H_DIM;
#pragma unroll
            for (int p = 0; p < 2; p++) {
                pa[p][0] = xp0[p][kk];     pa[p][1] = xp1[p][kk];
                pa[p][2] = xp0[p][kk + 4]; pa[p][3] = xp1[p][kk + 4];
            }
#pragma unroll
            for (int p = 0; p < 4; p++) {
                pg[p][0] = bgp[p][bo]; pg[p][1] = bgp[p][bo + 4 * (size_t)H_DIM];
                pu[p][0] = bup[p][bo]; pu[p][1] = bup[p][bo + 4 * (size_t)H_DIM];
            }
        }

        // compute on buf
        const uint32_t ab = buf * 2048, bb = buf * 2048;
#pragma unroll
        for (int kt = 0; kt < 2; kt++) {
            uint4 a[4];
#pragma unroll
            for (int mf = 0; mf < 4; mf++)
                a[mf] = *(const uint4*)&As[ab + (((wm * 4 + mf) * 2 + kt) * 32 + lane) * 4];
            uint2 fg[4], fu[4];
#pragma unroll
            for (int nf = 0; nf < 4; nf++) {
                const uint32_t o = (((wn * 4 + nf) * 2 + kt) * 32 + lane) * 2;
                fg[nf] = *(const uint2*)&Bg[bb + o];
                fu[nf] = *(const uint2*)&Bu[bb + o];
            }
#pragma unroll
            for (int mf = 0; mf < 4; mf++)
#pragma unroll
                for (int nf = 0; nf < 4; nf++) {
                    mma1688(accg[mf][nf], a[mf].x, a[mf].y, a[mf].z, a[mf].w,
                            fg[nf].x, fg[nf].y);
                    mma1688(accu[mf][nf], a[mf].x, a[mf].y, a[mf].z, a[mf].w,
                            fu[nf].x, fu[nf].y);
                }
        }

        if (pre) {
            const int nb = buf ^ 1;
            const uint32_t ao = nb * 2048, bo2 = nb * 2048;
#pragma unroll
            for (int p = 0; p < 2; p++)
                *(uint4*)&As[ao + a_sts[p]] = make_uint4(
                    tf32_rna(pa[p][0]), tf32_rna(pa[p][1]),
                    tf32_rna(pa[p][2]), tf32_rna(pa[p][3]));
#pragma unroll
            for (int p = 0; p < 4; p++) {
                *(uint2*)&Bg[bo2 + b_sts[p]] = make_uint2(tf32_rna(pg[p][0]), tf32_rna(pg[p][1]));
                *(uint2*)&Bu[bo2 + b_sts[p]] = make_uint2(tf32_rna(pu[p][0]), tf32_rna(pu[p][1]));
            }
        }
        __syncthreads();
        buf ^= 1;
    }

    // ---- epilogue: SwiGLU -> g_act ----
#pragma unroll
    for (int mf = 0; mf < 4; mf++) {
        const int r = row0 + wm * 64 + mf * 16 + g;
#pragma unroll
        for (int nf = 0; nf < 4; nf++) {
            const int col = col0 + wn * 32 + nf * 8 + 2 * t;
            if (r < n_e) {
                float2 o;
                o.x = silu(accg[mf][nf][0]) * accu[mf][nf][0];
                o.y = silu(accg[mf][nf][1]) * accu[mf][nf][1];
                *(float2*)(g_act + ((size_t)e * CAP + r) * H_DIM + col) = o;
            }
            if (r + 8 < n_e) {
                float2 o;
                o.x = silu(accg[mf][nf][2]) * accu[mf][nf][2];
                o.y = silu(accg[mf][nf][3]) * accu[mf][nf][3];
                *(float2*)(g_act + ((size_t)e * CAP + r + 8) * H_DIM + col) = o;
            }
        }
    }
}

// ---------------- kernel 3: grouped GEMM2 (tf32 mma, weighted y) ------------
// CTA 128(M) x 256(D), 8 warps (2M x 4N), warp 64x64.
// dyn smem u32: A[0,4096) buf stride 2048; B[4096,12288) buf stride 4096.
__global__ __launch_bounds__(256) void gemm2_kernel(const float* __restrict__ Wd)
{
    const int e = blockIdx.z;
    const int n_e = min(g_counts[e], CAP);
    const int row0 = blockIdx.x * 128;
    if (row0 >= n_e) return;
    const int col0 = blockIdx.y * 256;

    extern __shared__ uint32_t su[];
    uint32_t* As = su;
    uint32_t* Bs = su + 4096;
    __shared__ float sw[128];

    const int tid = threadIdx.x, lane = tid & 31, wid = tid >> 5;
    const int g = lane >> 2, t = lane & 3;

    if (tid < 128) {
        const int r = row0 + tid;
        sw[tid] = (r < n_e) ? g_slot_weight[e * CAP + r] : 0.f;
    }
    __syncthreads();

    // ---- staging descriptors ----
    const float* ap0[2]; const float* ap1[2]; uint32_t a_sts[2];
    const float* act_b = g_act + ((size_t)e * CAP + row0) * H_DIM;
#pragma unroll
    for (int p = 0; p < 2; p++) {
        const int tile = (tid >> 5) + 8 * p;        // 0..15
        const int mt = tile >> 1, kta = tile & 1;
        const int r0 = 16 * mt + g;
        ap0[p] = act_b + (size_t)r0 * H_DIM + 8 * kta + t;
        ap1[p] = act_b + (size_t)(r0 + 8) * H_DIM + 8 * kta + t;
        a_sts[p] = (uint32_t)(tile * 32 + lane) * 4;
    }
    const float* wd_e = Wd + (size_t)e * H_DIM * D_DIM;
    const float* bp[8]; uint32_t b_sts[8];
#pragma unroll
    for (int p = 0; p < 8; p++) {
        const int tile = (tid >> 5) + 8 * p;        // 0..63
        const int nt = tile >> 1, ktb = tile & 1;
        const int n = col0 + 8 * nt + g;
        bp[p] = wd_e + (size_t)(8 * ktb + t) * D_DIM + n;
        b_sts[p] = (uint32_t)(tile * 32 + lane) * 2;
    }

    const int wm = wid >> 2, wn = wid & 3;
    float acc[4][8][4] = {};

    const int NCH = H_DIM / 16;  // 24

    // ---- prologue ----
#pragma unroll
    for (int p = 0; p < 2; p++)
        *(uint4*)&As[a_sts[p]] = make_uint4(
            tf32_rna(ap0[p][0]), tf32_rna(ap1[p][0]),
            tf32_rna(ap0[p][4]), tf32_rna(ap1[p][4]));
#pragma unroll
    for (int p = 0; p < 8; p++)
        *(uint2*)&Bs[b_sts[p]] = make_uint2(
            tf32_rna(bp[p][0]), tf32_rna(bp[p][4 * (size_t)D_DIM]));
    __syncthreads();

    int buf = 0;
    for (int c = 0; c < NCH; c++) {
        float pa[2][4], pb[8][2];
        const bool pre = (c + 1 < NCH);
        if (pre) {
            const int kk = (c + 1) * 16;
            const size_t bo = (size_t)kk * D_DIM;
#pragma unroll
            for (int p = 0; p < 2; p++) {
                pa[p][0] = ap0[p][kk];     pa[p][1] = ap1[p][kk];
                pa[p][2] = ap0[p][kk + 4]; pa[p][3] = ap1[p][kk + 4];
            }
#pragma unroll
            for (int p = 0; p < 8; p++) {
                pb[p][0] = bp[p][bo];
                pb[p][1] = bp[p][bo + 4 * (size_t)D_DIM];
            }
        }

        const uint32_t ab = buf * 2048, bb = buf * 4096;
#pragma unroll
        for (int kt = 0; kt < 2; kt++) {
            uint4 a[4];
#pragma unroll
            for (int mf = 0; mf < 4; mf++)
                a[mf] = *(const uint4*)&As[ab + (((wm * 4 + mf) * 2 + kt) * 32 + lane) * 4];
            uint2 fb[8];
#pragma unroll
            for (int nf = 0; nf < 8; nf++)
                fb[nf] = *(const uint2*)&Bs[bb + (((wn * 8 + nf) * 2 + kt) * 32 + lane) * 2];
#pragma unroll
            for (int mf = 0; mf < 4; mf++)
#pragma unroll
                for (int nf = 0; nf < 8; nf++)
                    mma1688(acc[mf][nf], a[mf].x, a[mf].y, a[mf].z, a[mf].w,
                            fb[nf].x, fb[nf].y);
        }

        if (pre) {
            const int nb = buf ^ 1;
#pragma unroll
            for (int p = 0; p < 2; p++)
                *(uint4*)&As[nb * 2048 + a_sts[p]] = make_uint4(
                    tf32_rna(pa[p][0]), tf32_rna(pa[p][1]),
                    tf32_rna(pa[p][2]), tf32_rna(pa[p][3]));
#pragma unroll
            for (int p = 0; p < 8; p++)
                *(uint2*)&Bs[nb * 4096 + b_sts[p]] =
                    make_uint2(tf32_rna(pb[p][0]), tf32_rna(pb[p][1]));
        }
        __syncthreads();
        buf ^= 1;
    }

    // ---- epilogue: weight-scale -> g_y ----
#pragma unroll
    for (int mf = 0; mf < 4; mf++) {
        const int ml = wm * 64 + mf * 16 + g;
        const int r = row0 + ml;
        const float w1 = sw[ml], w2 = sw[ml + 8];
#pragma unroll
        for (int nf = 0; nf < 8; nf++) {
            const int col = col0 + wn * 64 + nf * 8 + 2 * t;
            if (r < n_e) {
                float2 o = { w1 * acc[mf][nf][0], w1 * acc[mf][nf][1] };
                *(float2*)(g_y + ((size_t)e * CAP + r) * D_DIM + col) = o;
            }
            if (r + 8 < n_e) {
                float2 o = { w2 * acc[mf][nf][2], w2 * acc[mf][nf][3] };
                *(float2*)(g_y + ((size_t)e * CAP + r + 8) * D_DIM + col) = o;
            }
        }
    }
}

// ---------------- kernel 4: combine (gather-sum per token) ------------------
__global__ __launch_bounds__(192) void combine_kernel(float* __restrict__ out)
{
    const int tk = blockIdx.x;
    const int tid = threadIdx.x;
    __shared__ int slots[TOPK];
    if (tid < TOPK) slots[tid] = g_tok_slot[tk * TOPK + tid];
    __syncthreads();

    float4 a0 = make_float4(0.f, 0.f, 0.f, 0.f);
    float4 a1 = a0;
#pragma unroll
    for (int k = 0; k < TOPK; k++) {
        const int s = slots[k];
        if (s < 0) continue;
        const float4* row = (const float4*)(g_y + (size_t)s * D_DIM);
        float4 v0 = row[tid * 2], v1 = row[tid * 2 + 1];
        a0.x += v0.x; a0.y += v0.y; a0.z += v0.z; a0.w += v0.w;
        a1.x += v1.x; a1.y += v1.y; a1.z += v1.z; a1.w += v1.w;
    }
    float4* o = (float4*)(out + (size_t)tk * D_DIM);
    o[tid * 2] = a0;
    o[tid * 2 + 1] = a1;
}

// ---------------- launcher --------------------------------------------------
extern "C" void kernel_launch(void* const* d_in, const int* in_sizes, int n_in,
                              void* d_out, int out_size)
{
    const float* x      = (const float*)d_in[0];
    const float* gate_w = (const float*)d_in[1];
    const float* W_gate = (const float*)d_in[2];
    const float* W_up   = (const float*)d_in[3];
    const float* W_down = (const float*)d_in[4];
    float* out = (float*)d_out;

    const int router_smem = 8 * D_DIM * 4 + 8 * E_NUM * 4;  // 51200
    const int gemm_smem = 12288 * 4;                        // 49152
    cudaFuncSetAttribute(router_kernel,
                         cudaFuncAttributeMaxDynamicSharedMemorySize, router_smem);
    cudaFuncSetAttribute(gemm1_kernel,
                         cudaFuncAttributeMaxDynamicSharedMemorySize, gemm_smem);
    cudaFuncSetAttribute(gemm2_kernel,
                         cudaFuncAttributeMaxDynamicSharedMemorySize, gemm_smem);

    init_kernel<<<1, 64>>>();
    router_kernel<<<T_NUM / 8, 256, router_smem>>>(x, gate_w);
    gemm1_kernel<<<dim3(CAP / 128, H_DIM / 128, E_NUM), 256, gemm_smem>>>(
        x, W_gate, W_up);
    gemm2_kernel<<<dim3(CAP / 128, D_DIM / 256, E_NUM), 256, gemm_smem>>>(W_down);
    combine_kernel<<<T_NUM, 192>>>(out);
}

// round 6
// speedup vs baseline: 1.2657x; 1.2657x over previous
#include <cuda_runtime.h>
#include <cuda_fp16.h>
#include <math.h>
#include <stdint.h>

#define D_DIM 1536
#define E_NUM 64
#define H_DIM 384
#define TOPK  8
#define CAP   1024
#define T_NUM 4096

// ---------------- scratch (static device globals; no allocations) ----------
__device__ __align__(16) int    g_counts[E_NUM];
__device__ __align__(16) int    g_slot_token[E_NUM * CAP];
__device__ __align__(16) float  g_slot_weight[E_NUM * CAP];
__device__ __align__(16) int    g_tok_slot[T_NUM * TOPK];
__device__ __align__(16) __half g_act[(size_t)E_NUM * CAP * H_DIM]; // ~50 MB (fp16)
__device__ __align__(16) float  g_y[(size_t)E_NUM * CAP * D_DIM];   // ~402 MB

// ---------------- helpers ----------------------------------------------------
__device__ __forceinline__ uint32_t pack_h2(float lo, float hi) {
    __half2 h = __floats2half2_rn(lo, hi);   // .x = lo (low 16 bits)
    return *(uint32_t*)&h;
}
__device__ __forceinline__ void mma16816(float c[4],
                                         uint32_t a0, uint32_t a1, uint32_t a2, uint32_t a3,
                                         uint32_t b0, uint32_t b1) {
    asm volatile(
        "mma.sync.aligned.m16n8k16.row.col.f32.f16.f16.f32 "
        "{%0,%1,%2,%3}, {%4,%5,%6,%7}, {%8,%9}, {%0,%1,%2,%3};"
        : "+f"(c[0]), "+f"(c[1]), "+f"(c[2]), "+f"(c[3])
        : "r"(a0), "r"(a1), "r"(a2), "r"(a3), "r"(b0), "r"(b1));
}
__device__ __forceinline__ float silu(float g) { return g / (1.f + expf(-g)); }

// ---------------- kernel 0: init counters -----------------------------------
__global__ void init_kernel() {
    if (threadIdx.x < E_NUM) g_counts[threadIdx.x] = 0;
}

// ---------------- kernel 1: router ------------------------------------------
extern __shared__ float s_dyn[];

__global__ __launch_bounds__(256) void router_kernel(
    const float* __restrict__ x, const float* __restrict__ gate_w)
{
    float (*xs)[D_DIM] = (float (*)[D_DIM])s_dyn;
    float (*lg)[E_NUM] = (float (*)[E_NUM])(s_dyn + 8 * D_DIM);

    const int tid = threadIdx.x;
    const int t0 = blockIdx.x * 8;

    const float4* xg = (const float4*)(x + (size_t)t0 * D_DIM);
    float4* xs4 = (float4*)xs;
    for (int i = tid; i < 8 * D_DIM / 4; i += 256) xs4[i] = xg[i];
    __syncthreads();

    const int warp = tid >> 5, lane = tid & 31;

    for (int j = 0; j < 8; j++) {
        const int e = warp * 8 + j;
        const float4* gr = (const float4*)(gate_w + (size_t)e * D_DIM);
        float acc[8];
#pragma unroll
        for (int t = 0; t < 8; t++) acc[t] = 0.f;
        for (int d4 = lane; d4 < D_DIM / 4; d4 += 32) {
            float4 g = gr[d4];
#pragma unroll
            for (int t = 0; t < 8; t++) {
                float4 xv = *(const float4*)(&xs[t][d4 * 4]);
                acc[t] = fmaf(g.x, xv.x, fmaf(g.y, xv.y,
                          fmaf(g.z, xv.z, fmaf(g.w, xv.w, acc[t]))));
            }
        }
#pragma unroll
        for (int off = 16; off > 0; off >>= 1)
#pragma unroll
            for (int t = 0; t < 8; t++)
                acc[t] += __shfl_xor_sync(0xffffffffu, acc[t], off);
        if (lane == 0)
#pragma unroll
            for (int t = 0; t < 8; t++) lg[t][e] = acc[t];
    }
    __syncthreads();

    {
        const int t = warp;
        float v0 = lg[t][lane];
        float v1 = lg[t][lane + 32];
        float m = fmaxf(v0, v1);
#pragma unroll
        for (int off = 16; off > 0; off >>= 1)
            m = fmaxf(m, __shfl_xor_sync(0xffffffffu, m, off));
        float e0 = expf(v0 - m), e1 = expf(v1 - m);
        float s = e0 + e1;
#pragma unroll
        for (int off = 16; off > 0; off >>= 1)
            s += __shfl_xor_sync(0xffffffffu, s, off);
        float p0 = e0 / s, p1 = e1 / s;

        float selw[TOPK];
        int   sele[TOPK];
#pragma unroll
        for (int k = 0; k < TOPK; k++) {
            float bv; int bi;
            if (p0 >= p1) { bv = p0; bi = lane; }
            else          { bv = p1; bi = lane + 32; }
#pragma unroll
            for (int off = 16; off > 0; off >>= 1) {
                float ov = __shfl_xor_sync(0xffffffffu, bv, off);
                int   oi = __shfl_xor_sync(0xffffffffu, bi, off);
                if (ov > bv || (ov == bv && oi < bi)) { bv = ov; bi = oi; }
            }
            selw[k] = bv; sele[k] = bi;
            if (bi == lane)      p0 = -1.f;
            if (bi == lane + 32) p1 = -1.f;
        }
        float wsum = 0.f;
#pragma unroll
        for (int k = 0; k < TOPK; k++) wsum += selw[k];

        if (lane == 0) {
            const int tok = t0 + t;
#pragma unroll
            for (int k = 0; k < TOPK; k++) {
                const int e = sele[k];
                const int pos = atomicAdd(&g_counts[e], 1);
                if (pos < CAP) {
                    g_slot_token[e * CAP + pos]  = tok;
                    g_slot_weight[e * CAP + pos] = selw[k] / wsum;
                    g_tok_slot[tok * TOPK + k]   = e * CAP + pos;
                } else {
                    g_tok_slot[tok * TOPK + k]   = -1;
                }
            }
        }
    }
}

// =============================================================================
// fp16 m16n8k16 fragment-major smem (per k=16 chunk):
//   A m-tile (16 rows): 32 lanes x uint4 {a0=(g,2t|2t+1), a1=(g+8,..),
//     a2=(g,2t+8|2t+9), a3=(g+8,..)} -> one LDS.128 per fragment.
//   B n-tile (8 cols): 32 lanes x uint2 {b0=(k=2t|2t+1, n=g), b1=(k+8 pair)}
//     -> one LDS.64 per fragment.
// Staging: warp == whole tile -> contiguous STS.128/STS.64, conflict-free.
// =============================================================================

// ---------------- kernel 2: grouped GEMM1 (fp16 mma, SwiGLU) ----------------
// CTA 128(M) x 64(H), 128 thr (4 warps, 2Mx2N), warp 64x32 DUAL (gate+up).
// dyn smem u32 per stage: A[0,1024) Bg[1024,1536) Bu[1536,2048); x2 stages.
__global__ __launch_bounds__(128, 2) void gemm1_kernel(
    const float* __restrict__ x,
    const float* __restrict__ Wg,
    const float* __restrict__ Wu)
{
    const int e = blockIdx.z;
    const int n_e = min(g_counts[e], CAP);
    const int row0 = blockIdx.x * 128;
    if (row0 >= n_e) return;
    const int col0 = blockIdx.y * 64;

    extern __shared__ uint32_t su[];
    __shared__ int stok[128];

    const int tid = threadIdx.x, lane = tid & 31, wid = tid >> 5;
    const int g = lane >> 2, t = lane & 3;

    if (tid < 128) {
        const int r = row0 + tid;
        stok[tid] = (r < n_e) ? g_slot_token[e * CAP + r] : 0;
    }
    __syncthreads();

    // ---- staging pointers (advance by +16 / +16*H per chunk) ----
    const float* xr0[2]; const float* xr1[2]; uint32_t a_sts[2];
#pragma unroll
    for (int p = 0; p < 2; p++) {
        const int tile = wid + 4 * p;             // mt 0..7
        const int r0 = 16 * tile + g;
        xr0[p] = x + (size_t)stok[r0] * D_DIM + 2 * t;
        xr1[p] = x + (size_t)stok[r0 + 8] * D_DIM + 2 * t;
        a_sts[p] = (uint32_t)(tile * 32 + lane) * 4;
    }
    const float* wg_e = Wg + (size_t)e * D_DIM * H_DIM;
    const float* wu_e = Wu + (size_t)e * D_DIM * H_DIM;
    const float* bgp[2]; const float* bup[2]; uint32_t b_sts[2];
#pragma unroll
    for (int p = 0; p < 2; p++) {
        const int nt = wid + 4 * p;               // 0..7
        const int n = col0 + 8 * nt + g;
        bgp[p] = wg_e + (size_t)(2 * t) * H_DIM + n;
        bup[p] = wu_e + (size_t)(2 * t) * H_DIM + n;
        b_sts[p] = 1024 + (uint32_t)(nt * 32 + lane) * 2;
    }

    const int wm = wid >> 1, wn = wid & 1;
    float accg[4][4][4] = {}, accu[4][4][4] = {};

    const int NCH = D_DIM / 16;  // 96

    // ---- prologue: stage chunk 0 ----
#pragma unroll
    for (int p = 0; p < 2; p++) {
        float2 v00 = *(const float2*)(xr0[p]);
        float2 v01 = *(const float2*)(xr0[p] + 8);
        float2 v10 = *(const float2*)(xr1[p]);
        float2 v11 = *(const float2*)(xr1[p] + 8);
        *(uint4*)&su[a_sts[p]] = make_uint4(
            pack_h2(v00.x, v00.y), pack_h2(v10.x, v10.y),
            pack_h2(v01.x, v01.y), pack_h2(v11.x, v11.y));
        xr0[p] += 16; xr1[p] += 16;
    }
#pragma unroll
    for (int p = 0; p < 2; p++) {
        *(uint2*)&su[b_sts[p]] = make_uint2(
            pack_h2(bgp[p][0], bgp[p][H_DIM]),
            pack_h2(bgp[p][8 * H_DIM], bgp[p][9 * H_DIM]));
        *(uint2*)&su[b_sts[p] + 512] = make_uint2(
            pack_h2(bup[p][0], bup[p][H_DIM]),
            pack_h2(bup[p][8 * H_DIM], bup[p][9 * H_DIM]));
        bgp[p] += 16 * H_DIM; bup[p] += 16 * H_DIM;
    }
    __syncthreads();

    int buf = 0;
    for (int c = 0; c < NCH; c++) {
        // prefetch next chunk
        float2 pa[2][4]; float pg[2][4], pu[2][4];
        const bool pre = (c + 1 < NCH);
        if (pre) {
#pragma unroll
            for (int p = 0; p < 2; p++) {
                pa[p][0] = *(const float2*)(xr0[p]);
                pa[p][1] = *(const float2*)(xr1[p]);
                pa[p][2] = *(const float2*)(xr0[p] + 8);
                pa[p][3] = *(const float2*)(xr1[p] + 8);
                xr0[p] += 16; xr1[p] += 16;
            }
#pragma unroll
            for (int p = 0; p < 2; p++) {
                pg[p][0] = bgp[p][0];          pg[p][1] = bgp[p][H_DIM];
                pg[p][2] = bgp[p][8 * H_DIM];  pg[p][3] = bgp[p][9 * H_DIM];
                pu[p][0] = bup[p][0];          pu[p][1] = bup[p][H_DIM];
                pu[p][2] = bup[p][8 * H_DIM];  pu[p][3] = bup[p][9 * H_DIM];
                bgp[p] += 16 * H_DIM; bup[p] += 16 * H_DIM;
            }
        }

        // compute on buf
        const uint32_t sb = buf * 2048;
        uint4 a[4];
#pragma unroll
        for (int mf = 0; mf < 4; mf++)
            a[mf] = *(const uint4*)&su[sb + ((wm * 4 + mf) * 32 + lane) * 4];
        uint2 fg[4], fu[4];
#pragma unroll
        for (int nf = 0; nf < 4; nf++) {
            const uint32_t o = sb + 1024 + ((wn * 4 + nf) * 32 + lane) * 2;
            fg[nf] = *(const uint2*)&su[o];
            fu[nf] = *(const uint2*)&su[o + 512];
        }
#pragma unroll
        for (int mf = 0; mf < 4; mf++)
#pragma unroll
            for (int nf = 0; nf < 4; nf++) {
                mma16816(accg[mf][nf], a[mf].x, a[mf].y, a[mf].z, a[mf].w,
                         fg[nf].x, fg[nf].y);
                mma16816(accu[mf][nf], a[mf].x, a[mf].y, a[mf].z, a[mf].w,
                         fu[nf].x, fu[nf].y);
            }

        if (pre) {
            const uint32_t nb = (buf ^ 1) * 2048;
#pragma unroll
            for (int p = 0; p < 2; p++)
                *(uint4*)&su[nb + a_sts[p]] = make_uint4(
                    pack_h2(pa[p][0].x, pa[p][0].y), pack_h2(pa[p][1].x, pa[p][1].y),
                    pack_h2(pa[p][2].x, pa[p][2].y), pack_h2(pa[p][3].x, pa[p][3].y));
#pragma unroll
            for (int p = 0; p < 2; p++) {
                *(uint2*)&su[nb + b_sts[p]] = make_uint2(
                    pack_h2(pg[p][0], pg[p][1]), pack_h2(pg[p][2], pg[p][3]));
                *(uint2*)&su[nb + b_sts[p] + 512] = make_uint2(
                    pack_h2(pu[p][0], pu[p][1]), pack_h2(pu[p][2], pu[p][3]));
            }
        }
        __syncthreads();
        buf ^= 1;
    }

    // ---- epilogue: SwiGLU -> g_act (fp16, k-paired) ----
    uint32_t* actu = (uint32_t*)(g_act + (size_t)e * CAP * H_DIM);
#pragma unroll
    for (int mf = 0; mf < 4; mf++) {
        const int r = row0 + wm * 64 + mf * 16 + g;
#pragma unroll
        for (int nf = 0; nf < 4; nf++) {
            const int col = col0 + wn * 32 + nf * 8 + 2 * t;
            if (r < n_e) {
                actu[(size_t)r * (H_DIM / 2) + col / 2] = pack_h2(
                    silu(accg[mf][nf][0]) * accu[mf][nf][0],
                    silu(accg[mf][nf][1]) * accu[mf][nf][1]);
            }
            if (r + 8 < n_e) {
                actu[(size_t)(r + 8) * (H_DIM / 2) + col / 2] = pack_h2(
                    silu(accg[mf][nf][2]) * accu[mf][nf][2],
                    silu(accg[mf][nf][3]) * accu[mf][nf][3]);
            }
        }
    }
}

// ---------------- kernel 3: grouped GEMM2 (fp16 mma, weighted y) ------------
// CTA 128(M) x 128(D), 128 thr (4 warps, 2Mx2N), warp 64x64.
// dyn smem u32 per stage: A[0,1024) B[1024,2048); x2 stages.
__global__ __launch_bounds__(128, 2) void gemm2_kernel(const float* __restrict__ Wd)
{
    const int e = blockIdx.z;
    const int n_e = min(g_counts[e], CAP);
    const int row0 = blockIdx.x * 128;
    if (row0 >= n_e) return;
    const int col0 = blockIdx.y * 128;

    extern __shared__ uint32_t su[];
    __shared__ float sw[128];

    const int tid = threadIdx.x, lane = tid & 31, wid = tid >> 5;
    const int g = lane >> 2, t = lane & 3;

    if (tid < 128) {
        const int r = row0 + tid;
        sw[tid] = (r < n_e) ? g_slot_weight[e * CAP + r] : 0.f;
    }
    __syncthreads();

    // ---- staging pointers ----
    const uint32_t* actu = (const uint32_t*)(g_act + ((size_t)e * CAP + row0) * H_DIM);
    const uint32_t* ap0[2]; const uint32_t* ap1[2]; uint32_t a_sts[2];
#pragma unroll
    for (int p = 0; p < 2; p++) {
        const int tile = wid + 4 * p;             // mt 0..7
        const int r0 = 16 * tile + g;
        ap0[p] = actu + (size_t)r0 * (H_DIM / 2) + t;
        ap1[p] = actu + (size_t)(r0 + 8) * (H_DIM / 2) + t;
        a_sts[p] = (uint32_t)(tile * 32 + lane) * 4;
    }
    const float* wd_e = Wd + (size_t)e * H_DIM * D_DIM;
    const float* bp[4]; uint32_t b_sts[4];
#pragma unroll
    for (int p = 0; p < 4; p++) {
        const int nt = wid + 4 * p;               // 0..15
        const int n = col0 + 8 * nt + g;
        bp[p] = wd_e + (size_t)(2 * t) * D_DIM + n;
        b_sts[p] = 1024 + (uint32_t)(nt * 32 + lane) * 2;
    }

    const int wm = wid >> 1, wn = wid & 1;
    float acc[4][8][4] = {};

    const int NCH = H_DIM / 16;  // 24

    // ---- prologue ----
#pragma unroll
    for (int p = 0; p < 2; p++) {
        *(uint4*)&su[a_sts[p]] = make_uint4(ap0[p][0], ap1[p][0], ap0[p][4], ap1[p][4]);
        ap0[p] += 8; ap1[p] += 8;
    }
#pragma unroll
    for (int p = 0; p < 4; p++) {
        *(uint2*)&su[b_sts[p]] = make_uint2(
            pack_h2(bp[p][0], bp[p][D_DIM]),
            pack_h2(bp[p][8 * D_DIM], bp[p][9 * D_DIM]));
        bp[p] += 16 * D_DIM;
    }
    __syncthreads();

    int buf = 0;
    for (int c = 0; c < NCH; c++) {
        uint32_t pa[2][4]; float pb[4][4];
        const bool pre = (c + 1 < NCH);
        if (pre) {
#pragma unroll
            for (int p = 0; p < 2; p++) {
                pa[p][0] = ap0[p][0]; pa[p][1] = ap1[p][0];
                pa[p][2] = ap0[p][4]; pa[p][3] = ap1[p][4];
                ap0[p] += 8; ap1[p] += 8;
            }
#pragma unroll
            for (int p = 0; p < 4; p++) {
                pb[p][0] = bp[p][0];          pb[p][1] = bp[p][D_DIM];
                pb[p][2] = bp[p][8 * D_DIM];  pb[p][3] = bp[p][9 * D_DIM];
                bp[p] += 16 * D_DIM;
            }
        }

        const uint32_t sb = buf * 2048;
        uint4 a[4];
#pragma unroll
        for (int mf = 0; mf < 4; mf++)
            a[mf] = *(const uint4*)&su[sb + ((wm * 4 + mf) * 32 + lane) * 4];
        uint2 fb[8];
#pragma unroll
        for (int nf = 0; nf < 8; nf++)
            fb[nf] = *(const uint2*)&su[sb + 1024 + ((wn * 8 + nf) * 32 + lane) * 2];
#pragma unroll
        for (int mf = 0; mf < 4; mf++)
#pragma unroll
            for (int nf = 0; nf < 8; nf++)
                mma16816(acc[mf][nf], a[mf].x, a[mf].y, a[mf].z, a[mf].w,
                         fb[nf].x, fb[nf].y);

        if (pre) {
            const uint32_t nb = (buf ^ 1) * 2048;
#pragma unroll
            for (int p = 0; p < 2; p++)
                *(uint4*)&su[nb + a_sts[p]] =
                    make_uint4(pa[p][0], pa[p][1], pa[p][2], pa[p][3]);
#pragma unroll
            for (int p = 0; p < 4; p++)
                *(uint2*)&su[nb + b_sts[p]] = make_uint2(
                    pack_h2(pb[p][0], pb[p][1]), pack_h2(pb[p][2], pb[p][3]));
        }
        __syncthreads();
        buf ^= 1;
    }

    // ---- epilogue: weight-scale -> g_y ----
#pragma unroll
    for (int mf = 0; mf < 4; mf++) {
        const int ml = wm * 64 + mf * 16 + g;
        const int r = row0 + ml;
        const float w1 = sw[ml], w2 = sw[ml + 8];
#pragma unroll
        for (int nf = 0; nf < 8; nf++) {
            const int col = col0 + wn * 64 + nf * 8 + 2 * t;
            if (r < n_e) {
                float2 o = { w1 * acc[mf][nf][0], w1 * acc[mf][nf][1] };
                *(float2*)(g_y + ((size_t)e * CAP + r) * D_DIM + col) = o;
            }
            if (r + 8 < n_e) {
                float2 o = { w2 * acc[mf][nf][2], w2 * acc[mf][nf][3] };
                *(float2*)(g_y + ((size_t)e * CAP + r + 8) * D_DIM + col) = o;
            }
        }
    }
}

// ---------------- kernel 4: combine (gather-sum per token) ------------------
__global__ __launch_bounds__(192) void combine_kernel(float* __restrict__ out)
{
    const int tk = blockIdx.x;
    const int tid = threadIdx.x;
    __shared__ int slots[TOPK];
    if (tid < TOPK) slots[tid] = g_tok_slot[tk * TOPK + tid];
    __syncthreads();

    float4 a0 = make_float4(0.f, 0.f, 0.f, 0.f);
    float4 a1 = a0;
#pragma unroll
    for (int k = 0; k < TOPK; k++) {
        const int s = slots[k];
        if (s < 0) continue;
        const float4* row = (const float4*)(g_y + (size_t)s * D_DIM);
        float4 v0 = row[tid * 2], v1 = row[tid * 2 + 1];
        a0.x += v0.x; a0.y += v0.y; a0.z += v0.z; a0.w += v0.w;
        a1.x += v1.x; a1.y += v1.y; a1.z += v1.z; a1.w += v1.w;
    }
    float4* o = (float4*)(out + (size_t)tk * D_DIM);
    o[tid * 2] = a0;
    o[tid * 2 + 1] = a1;
}

// ---------------- launcher --------------------------------------------------
extern "C" void kernel_launch(void* const* d_in, const int* in_sizes, int n_in,
                              void* d_out, int out_size)
{
    const float* x      = (const float*)d_in[0];
    const float* gate_w = (const float*)d_in[1];
    const float* W_gate = (const float*)d_in[2];
    const float* W_up   = (const float*)d_in[3];
    const float* W_down = (const float*)d_in[4];
    float* out = (float*)d_out;

    const int router_smem = 8 * D_DIM * 4 + 8 * E_NUM * 4;  // 51200
    const int gemm_smem = 4096 * 4;                         // 16384
    cudaFuncSetAttribute(router_kernel,
                         cudaFuncAttributeMaxDynamicSharedMemorySize, router_smem);

    init_kernel<<<1, 64>>>();
    router_kernel<<<T_NUM / 8, 256, router_smem>>>(x, gate_w);
    gemm1_kernel<<<dim3(CAP / 128, H_DIM / 64, E_NUM), 128, gemm_smem>>>(
        x, W_gate, W_up);
    gemm2_kernel<<<dim3(CAP / 128, D_DIM / 128, E_NUM), 128, gemm_smem>>>(W_down);
    combine_kernel<<<T_NUM, 192>>>(out);
}

// round 7
// speedup vs baseline: 1.8633x; 1.4721x over previous
#include <cuda_runtime.h>
#include <cuda_fp16.h>
#include <math.h>
#include <stdint.h>

#define D_DIM 1536
#define E_NUM 64
#define H_DIM 384
#define TOPK  8
#define CAP   1024
#define T_NUM 4096

// ---------------- scratch (static device globals; no allocations) ----------
__device__ __align__(16) int      g_counts[E_NUM];
__device__ __align__(16) int      g_slot_token[E_NUM * CAP];
__device__ __align__(16) float    g_slot_weight[E_NUM * CAP];
__device__ __align__(16) int      g_tok_slot[T_NUM * TOPK];
__device__ __align__(16) __half   g_xh[(size_t)T_NUM * D_DIM];                // 12.6 MB
__device__ __align__(16) uint32_t g_wgf[(size_t)E_NUM * 96 * 48 * 32 * 2];    // 75 MB
__device__ __align__(16) uint32_t g_wuf[(size_t)E_NUM * 96 * 48 * 32 * 2];    // 75 MB
__device__ __align__(16) uint32_t g_wdf[(size_t)E_NUM * 24 * 192 * 32 * 2];   // 75 MB
__device__ __align__(16) uint32_t g_actf[(size_t)E_NUM * 64 * 24 * 128];      // 50 MB
__device__ __align__(16) float    g_y[(size_t)E_NUM * CAP * D_DIM];           // 402 MB

// ---------------- helpers ----------------------------------------------------
__device__ __forceinline__ uint32_t pack_h2(float lo, float hi) {
    __half2 h = __floats2half2_rn(lo, hi);
    return *(uint32_t*)&h;
}
__device__ __forceinline__ uint32_t smem_u32(const void* p) {
    return (uint32_t)__cvta_generic_to_shared(p);
}
__device__ __forceinline__ void cp16(uint32_t dst, const void* src) {
    asm volatile("cp.async.cg.shared.global [%0], [%1], 16;"
                 :: "r"(dst), "l"(src) : "memory");
}
__device__ __forceinline__ void cp_commit() {
    asm volatile("cp.async.commit_group;" ::: "memory");
}
template <int N>
__device__ __forceinline__ void cp_wait() {
    asm volatile("cp.async.wait_group %0;" :: "n"(N) : "memory");
}
__device__ __forceinline__ void ldmx4(uint32_t& a0, uint32_t& a1,
                                      uint32_t& a2, uint32_t& a3, uint32_t addr) {
    asm volatile("ldmatrix.sync.aligned.m8n8.x4.shared.b16 {%0,%1,%2,%3}, [%4];"
                 : "=r"(a0), "=r"(a1), "=r"(a2), "=r"(a3) : "r"(addr));
}
__device__ __forceinline__ void mma16816(float c[4],
                                         uint32_t a0, uint32_t a1, uint32_t a2, uint32_t a3,
                                         uint32_t b0, uint32_t b1) {
    asm volatile(
        "mma.sync.aligned.m16n8k16.row.col.f32.f16.f16.f32 "
        "{%0,%1,%2,%3}, {%4,%5,%6,%7}, {%8,%9}, {%0,%1,%2,%3};"
        : "+f"(c[0]), "+f"(c[1]), "+f"(c[2]), "+f"(c[3])
        : "r"(a0), "r"(a1), "r"(a2), "r"(a3), "r"(b0), "r"(b1));
}
__device__ __forceinline__ float silu(float g) { return g / (1.f + expf(-g)); }

// ---------------- kernel 0: init counters -----------------------------------
__global__ void init_kernel() {
    if (threadIdx.x < E_NUM) g_counts[threadIdx.x] = 0;
}

// ---------------- converters -------------------------------------------------
__global__ __launch_bounds__(256) void convert_x_kernel(const float* __restrict__ x) {
    const float4* x4 = (const float4*)x;
    uint2* xh2 = (uint2*)g_xh;
    const size_t n4 = (size_t)T_NUM * D_DIM / 4;
    for (size_t i = blockIdx.x * 256 + threadIdx.x; i < n4; i += (size_t)gridDim.x * 256) {
        float4 v = x4[i];
        xh2[i] = make_uint2(pack_h2(v.x, v.y), pack_h2(v.z, v.w));
    }
}

// W[E][D][H] (k=D, n=H) -> fragment-major fp16 [e][kc=96][nt=48][lane] uint2
__global__ __launch_bounds__(256) void convert_gu_kernel(
    const float* __restrict__ Wg, const float* __restrict__ Wu)
{
    const int kc = blockIdx.x, e = blockIdx.y;
    const int tid = threadIdx.x, lane = tid & 31, g = lane >> 2, t = lane & 3;
    const size_t wbase = (size_t)e * D_DIM * H_DIM + (size_t)(16 * kc + 2 * t) * H_DIM;
    const float* wg0 = Wg + wbase;
    const float* wu0 = Wu + wbase;
    uint2* og = (uint2*)g_wgf;
    uint2* ou = (uint2*)g_wuf;
#pragma unroll
    for (int p = 0; p < 6; p++) {
        const int nt = (tid >> 5) + 8 * p;
        const int n = 8 * nt + g;
        const size_t oi = ((size_t)(e * 96 + kc) * 48 + nt) * 32 + lane;
        og[oi] = make_uint2(pack_h2(wg0[n], wg0[H_DIM + n]),
                            pack_h2(wg0[8 * H_DIM + n], wg0[9 * H_DIM + n]));
        ou[oi] = make_uint2(pack_h2(wu0[n], wu0[H_DIM + n]),
                            pack_h2(wu0[8 * H_DIM + n], wu0[9 * H_DIM + n]));
    }
}

// W_down[E][H][D] (k=H, n=D) -> [e][kc=24][nt=192][lane] uint2
__global__ __launch_bounds__(256) void convert_d_kernel(const float* __restrict__ Wd)
{
    const int kc = blockIdx.x, e = blockIdx.y;
    const int tid = threadIdx.x, lane = tid & 31, g = lane >> 2, t = lane & 3;
    const float* wd0 = Wd + (size_t)e * H_DIM * D_DIM + (size_t)(16 * kc + 2 * t) * D_DIM;
    uint2* od = (uint2*)g_wdf;
#pragma unroll
    for (int p = 0; p < 24; p++) {
        const int nt = (tid >> 5) + 8 * p;
        const int n = 8 * nt + g;
        od[((size_t)(e * 24 + kc) * 192 + nt) * 32 + lane] =
            make_uint2(pack_h2(wd0[n], wd0[D_DIM + n]),
                       pack_h2(wd0[8 * D_DIM + n], wd0[9 * D_DIM + n]));
    }
}

// ---------------- kernel: router --------------------------------------------
extern __shared__ float s_dyn[];

__global__ __launch_bounds__(256) void router_kernel(
    const float* __restrict__ x, const float* __restrict__ gate_w)
{
    float (*xs)[D_DIM] = (float (*)[D_DIM])s_dyn;
    float (*lg)[E_NUM] = (float (*)[E_NUM])(s_dyn + 8 * D_DIM);

    const int tid = threadIdx.x;
    const int t0 = blockIdx.x * 8;

    const float4* xg = (const float4*)(x + (size_t)t0 * D_DIM);
    float4* xs4 = (float4*)xs;
    for (int i = tid; i < 8 * D_DIM / 4; i += 256) xs4[i] = xg[i];
    __syncthreads();

    const int warp = tid >> 5, lane = tid & 31;

    for (int j = 0; j < 8; j++) {
        const int e = warp * 8 + j;
        const float4* gr = (const float4*)(gate_w + (size_t)e * D_DIM);
        float acc[8];
#pragma unroll
        for (int t = 0; t < 8; t++) acc[t] = 0.f;
        for (int d4 = lane; d4 < D_DIM / 4; d4 += 32) {
            float4 g = gr[d4];
#pragma unroll
            for (int t = 0; t < 8; t++) {
                float4 xv = *(const float4*)(&xs[t][d4 * 4]);
                acc[t] = fmaf(g.x, xv.x, fmaf(g.y, xv.y,
                          fmaf(g.z, xv.z, fmaf(g.w, xv.w, acc[t]))));
            }
        }
#pragma unroll
        for (int off = 16; off > 0; off >>= 1)
#pragma unroll
            for (int t = 0; t < 8; t++)
                acc[t] += __shfl_xor_sync(0xffffffffu, acc[t], off);
        if (lane == 0)
#pragma unroll
            for (int t = 0; t < 8; t++) lg[t][e] = acc[t];
    }
    __syncthreads();

    {
        const int t = warp;
        float v0 = lg[t][lane];
        float v1 = lg[t][lane + 32];
        float m = fmaxf(v0, v1);
#pragma unroll
        for (int off = 16; off > 0; off >>= 1)
            m = fmaxf(m, __shfl_xor_sync(0xffffffffu, m, off));
        float e0 = expf(v0 - m), e1 = expf(v1 - m);
        float s = e0 + e1;
#pragma unroll
        for (int off = 16; off > 0; off >>= 1)
            s += __shfl_xor_sync(0xffffffffu, s, off);
        float p0 = e0 / s, p1 = e1 / s;

        float selw[TOPK];
        int   sele[TOPK];
#pragma unroll
        for (int k = 0; k < TOPK; k++) {
            float bv; int bi;
            if (p0 >= p1) { bv = p0; bi = lane; }
            else          { bv = p1; bi = lane + 32; }
#pragma unroll
            for (int off = 16; off > 0; off >>= 1) {
                float ov = __shfl_xor_sync(0xffffffffu, bv, off);
                int   oi = __shfl_xor_sync(0xffffffffu, bi, off);
                if (ov > bv || (ov == bv && oi < bi)) { bv = ov; bi = oi; }
            }
            selw[k] = bv; sele[k] = bi;
            if (bi == lane)      p0 = -1.f;
            if (bi == lane + 32) p1 = -1.f;
        }
        float wsum = 0.f;
#pragma unroll
        for (int k = 0; k < TOPK; k++) wsum += selw[k];

        if (lane == 0) {
            const int tok = t0 + t;
#pragma unroll
            for (int k = 0; k < TOPK; k++) {
                const int e = sele[k];
                const int pos = atomicAdd(&g_counts[e], 1);
                if (pos < CAP) {
                    g_slot_token[e * CAP + pos]  = tok;
                    g_slot_weight[e * CAP + pos] = selw[k] / wsum;
                    g_tok_slot[tok * TOPK + k]   = e * CAP + pos;
                } else {
                    g_tok_slot[tok * TOPK + k]   = -1;
                }
            }
        }
    }
}

// ---------------- kernel: grouped GEMM1 (fp16 mma + cp.async, SwiGLU) --------
// CTA 128(M) x 64(H), 128 thr (4 warps 2Mx2N), warp 64x32 dual. 4-stage pipe.
// Stage (8KB): A swizzled row-major [0,4KB), Bg frags [4KB,6KB), Bu [6KB,8KB).
__global__ __launch_bounds__(128) void gemm1_kernel()
{
    const int e = blockIdx.z;
    const int n_e = min(g_counts[e], CAP);
    const int row0 = blockIdx.x * 128;
    if (row0 >= n_e) return;
    const int by = blockIdx.y;  // 0..5 (col0 = by*64)

    extern __shared__ uint32_t su[];  // 8192 u32
    __shared__ int stok[128];

    const int tid = threadIdx.x, lane = tid & 31, wid = tid >> 5;
    const int wm = wid >> 1, wn = wid & 1;
    const uint32_t sb = smem_u32(su);

    {
        const int r = row0 + tid;
        stok[tid] = (r < n_e) ? g_slot_token[e * CAP + r] : 0;
    }
    __syncthreads();

    const char* srcA = (const char*)g_xh + (size_t)stok[tid] * (D_DIM * 2);
    const uint32_t swA = ((tid >> 2) & 1) ? 16u : 0u;
    const uint32_t dA0 = sb + tid * 32 + swA;
    const uint32_t dA1 = sb + tid * 32 + (16u ^ swA);
    const char* srcG = (const char*)g_wgf +
        ((size_t)e * 96 * 48 + (size_t)by * 8) * 256 + tid * 16;
    const char* srcU = (const char*)g_wuf +
        ((size_t)e * 96 * 48 + (size_t)by * 8) * 256 + tid * 16;

    auto stage = [&](int c) {
        const uint32_t so = (uint32_t)(c & 3) * 8192;
        cp16(dA0 + so, srcA + (size_t)c * 32);
        cp16(dA1 + so, srcA + (size_t)c * 32 + 16);
        cp16(sb + so + 4096 + tid * 16, srcG + (size_t)c * 12288);
        cp16(sb + so + 6144 + tid * 16, srcU + (size_t)c * 12288);
    };
    stage(0); cp_commit();
    stage(1); cp_commit();
    stage(2); cp_commit();

    float accg[4][4][4] = {}, accu[4][4][4] = {};

    for (int c = 0; c < 96; c++) {
        cp_wait<2>();
        __syncthreads();
        if (c + 3 < 96) stage(c + 3);
        cp_commit();

        const uint32_t so = (uint32_t)(c & 3) * 8192;
        const uint32_t io = (c & 3) * 2048;
        uint32_t a[4][4];
#pragma unroll
        for (int mf = 0; mf < 4; mf++) {
            const int rl = (wm * 4 + mf) * 16 + (lane & 15);
            const uint32_t ad = sb + so + rl * 32 +
                ((((lane >> 4) ^ ((rl >> 2) & 1))) << 4);
            ldmx4(a[mf][0], a[mf][1], a[mf][2], a[mf][3], ad);
        }
        uint2 fg[4], fu[4];
#pragma unroll
        for (int nf = 0; nf < 4; nf++) {
            fg[nf] = *(const uint2*)&su[io + 1024 + ((wn * 4 + nf) * 32 + lane) * 2];
            fu[nf] = *(const uint2*)&su[io + 1536 + ((wn * 4 + nf) * 32 + lane) * 2];
        }
#pragma unroll
        for (int mf = 0; mf < 4; mf++)
#pragma unroll
            for (int nf = 0; nf < 4; nf++) {
                mma16816(accg[mf][nf], a[mf][0], a[mf][1], a[mf][2], a[mf][3],
                         fg[nf].x, fg[nf].y);
                mma16816(accu[mf][nf], a[mf][0], a[mf][1], a[mf][2], a[mf][3],
                         fu[nf].x, fu[nf].y);
            }
    }

    // epilogue: SwiGLU -> g_actf in gemm2 A-fragment-major layout
    uint4* actf4 = (uint4*)g_actf;
#pragma unroll
    for (int mf = 0; mf < 4; mf++) {
        const int mt = (row0 >> 4) + wm * 4 + mf;
#pragma unroll
        for (int j = 0; j < 2; j++) {
            const int kc2 = by * 4 + wn * 2 + j;
            const float v0 = silu(accg[mf][2 * j][0]) * accu[mf][2 * j][0];
            const float v1 = silu(accg[mf][2 * j][1]) * accu[mf][2 * j][1];
            const float v2 = silu(accg[mf][2 * j][2]) * accu[mf][2 * j][2];
            const float v3 = silu(accg[mf][2 * j][3]) * accu[mf][2 * j][3];
            const float w0 = silu(accg[mf][2 * j + 1][0]) * accu[mf][2 * j + 1][0];
            const float w1 = silu(accg[mf][2 * j + 1][1]) * accu[mf][2 * j + 1][1];
            const float w2 = silu(accg[mf][2 * j + 1][2]) * accu[mf][2 * j + 1][2];
            const float w3 = silu(accg[mf][2 * j + 1][3]) * accu[mf][2 * j + 1][3];
            actf4[((size_t)(e * 64 + mt) * 24 + kc2) * 32 + lane] =
                make_uint4(pack_h2(v0, v1), pack_h2(v2, v3),
                           pack_h2(w0, w1), pack_h2(w2, w3));
        }
    }
}

// ---------------- kernel: grouped GEMM2 (fp16 mma + cp.async, weighted y) ---
// CTA 128(M) x 128(D), 128 thr (4 warps 2Mx2N), warp 64x64. 4-stage pipe.
// Stage (8KB): A frags [0,4KB), B frags [4KB,8KB).
__global__ __launch_bounds__(128) void gemm2_kernel()
{
    const int e = blockIdx.z;
    const int n_e = min(g_counts[e], CAP);
    const int row0 = blockIdx.x * 128;
    if (row0 >= n_e) return;
    const int by = blockIdx.y;  // 0..11 (col0 = by*128)
    const int col0 = by * 128;

    extern __shared__ uint32_t su[];
    __shared__ float sw[128];

    const int tid = threadIdx.x, lane = tid & 31, wid = tid >> 5;
    const int wm = wid >> 1, wn = wid & 1;
    const uint32_t sb = smem_u32(su);

    {
        const int r = row0 + tid;
        sw[tid] = (r < n_e) ? g_slot_weight[e * CAP + r] : 0.f;
    }
    __syncthreads();

    // A sources: seg0 = tid (mt = tid>>5), seg1 = tid+128 (mt = (tid>>5)+4)
    const char* actb = (const char*)g_actf;
    const char* sA0 = actb +
        ((size_t)(e * 64 + (row0 >> 4) + (tid >> 5)) * 24) * 512 + (tid & 31) * 16;
    const char* sA1 = actb +
        ((size_t)(e * 64 + (row0 >> 4) + (tid >> 5) + 4) * 24) * 512 + (tid & 31) * 16;
    const char* sB = (const char*)g_wdf +
        ((size_t)e * 24 * 192 + (size_t)(by * 16)) * 256 + tid * 16;

    auto stage = [&](int c) {
        const uint32_t so = (uint32_t)(c & 3) * 8192;
        cp16(sb + so + tid * 16,        sA0 + (size_t)c * 512);
        cp16(sb + so + 2048 + tid * 16, sA1 + (size_t)c * 512);
        cp16(sb + so + 4096 + tid * 16,        sB + (size_t)c * 49152);
        cp16(sb + so + 4096 + 2048 + tid * 16, sB + (size_t)c * 49152 + 2048);
    };
    stage(0); cp_commit();
    stage(1); cp_commit();
    stage(2); cp_commit();

    float acc[4][8][4] = {};

    for (int c = 0; c < 24; c++) {
        cp_wait<2>();
        __syncthreads();
        if (c + 3 < 24) stage(c + 3);
        cp_commit();

        const uint32_t io = (c & 3) * 2048;
        uint4 a[4];
#pragma unroll
        for (int mf = 0; mf < 4; mf++)
            a[mf] = *(const uint4*)&su[io + ((wm * 4 + mf) * 32 + lane) * 4];
        uint2 fb[8];
#pragma unroll
        for (int nf = 0; nf < 8; nf++)
            fb[nf] = *(const uint2*)&su[io + 1024 + ((wn * 8 + nf) * 32 + lane) * 2];
#pragma unroll
        for (int mf = 0; mf < 4; mf++)
#pragma unroll
            for (int nf = 0; nf < 8; nf++)
                mma16816(acc[mf][nf], a[mf].x, a[mf].y, a[mf].z, a[mf].w,
                         fb[nf].x, fb[nf].y);
    }

    // epilogue: weight-scale rows -> g_y
    const int g = lane >> 2, t = lane & 3;
#pragma unroll
    for (int mf = 0; mf < 4; mf++) {
        const int ml = wm * 64 + mf * 16 + g;
        const int r = row0 + ml;
        const float w1 = sw[ml], w2 = sw[ml + 8];
#pragma unroll
        for (int nf = 0; nf < 8; nf++) {
            const int col = col0 + wn * 64 + nf * 8 + 2 * t;
            if (r < n_e) {
                float2 o = { w1 * acc[mf][nf][0], w1 * acc[mf][nf][1] };
                *(float2*)(g_y + ((size_t)e * CAP + r) * D_DIM + col) = o;
            }
            if (r + 8 < n_e) {
                float2 o = { w2 * acc[mf][nf][2], w2 * acc[mf][nf][3] };
                *(float2*)(g_y + ((size_t)e * CAP + r + 8) * D_DIM + col) = o;
            }
        }
    }
}

// ---------------- kernel: combine (gather-sum per token) --------------------
__global__ __launch_bounds__(192) void combine_kernel(float* __restrict__ out)
{
    const int tk = blockIdx.x;
    const int tid = threadIdx.x;
    __shared__ int slots[TOPK];
    if (tid < TOPK) slots[tid] = g_tok_slot[tk * TOPK + tid];
    __syncthreads();

    float4 a0 = make_float4(0.f, 0.f, 0.f, 0.f);
    float4 a1 = a0;
#pragma unroll
    for (int k = 0; k < TOPK; k++) {
        const int s = slots[k];
        if (s < 0) continue;
        const float4* row = (const float4*)(g_y + (size_t)s * D_DIM);
        float4 v0 = row[tid * 2], v1 = row[tid * 2 + 1];
        a0.x += v0.x; a0.y += v0.y; a0.z += v0.z; a0.w += v0.w;
        a1.x += v1.x; a1.y += v1.y; a1.z += v1.z; a1.w += v1.w;
    }
    float4* o = (float4*)(out + (size_t)tk * D_DIM);
    o[tid * 2] = a0;
    o[tid * 2 + 1] = a1;
}

// ---------------- launcher --------------------------------------------------
extern "C" void kernel_launch(void* const* d_in, const int* in_sizes, int n_in,
                              void* d_out, int out_size)
{
    const float* x      = (const float*)d_in[0];
    const float* gate_w = (const float*)d_in[1];
    const float* W_gate = (const float*)d_in[2];
    const float* W_up   = (const float*)d_in[3];
    const float* W_down = (const float*)d_in[4];
    float* out = (float*)d_out;

    const int router_smem = 8 * D_DIM * 4 + 8 * E_NUM * 4;  // 51200
    cudaFuncSetAttribute(router_kernel,
                         cudaFuncAttributeMaxDynamicSharedMemorySize, router_smem);

    init_kernel<<<1, 64>>>();
    convert_x_kernel<<<2048, 256>>>(x);
    convert_gu_kernel<<<dim3(96, 64), 256>>>(W_gate, W_up);
    convert_d_kernel<<<dim3(24, 64), 256>>>(W_down);
    router_kernel<<<T_NUM / 8, 256, router_smem>>>(x, gate_w);
    gemm1_kernel<<<dim3(CAP / 128, H_DIM / 64, E_NUM), 128, 32768>>>();
    gemm2_kernel<<<dim3(CAP / 128, D_DIM / 128, E_NUM), 128, 32768>>>();
    combine_kernel<<<T_NUM, 192>>>(out);
}